// round 13
// baseline (speedup 1.0000x reference)
#include <cuda_runtime.h>
#include <cuda_bf16.h>
#include <cuda_fp16.h>
#include <math.h>
#include <stdint.h>

#define MAXN 100000
#define NPAD 100096
#define MAXE 600000
#define DD 128

// ---------------- static device scratch (zero-initialized at load) ----------------
__device__ __align__(256) __half g_Y[8L * NPAD * DD];   // Y_r = S_r X_r (fp16)
__device__ __align__(256) __half g_Bt[8 * DD * DD];     // fp16(lam * W^T)
__device__ __align__(256) __half g_fI[MAXN * 2 * DD];   // node: 256B fsrc | 256B fdst (fp16)
__device__ float4 g_P[2 * MAXN];   // src-side: (el_f.ra, el_f.rb, er_r.ra, er_r.rb)
__device__ float4 g_Q[2 * MAXN];   // dst-side: (er_f.ra, er_f.rb, el_r.ra, el_r.rb)
__device__ float g_wal[8 * DD];
__device__ float g_war[8 * DD];
__device__ int   g_cnt[4 * MAXN];     // zeroed at load; re-zeroed by scan each run
__device__ int   g_rowptr[4 * MAXN];
__device__ int   g_cursor[4 * MAXN];
__device__ int   g_col[4 * MAXE];
__device__ unsigned g_w[4 * MAXE];    // per-slot half2(wa, wb)
// decoupled-lookback state (reset by last scan block each run)
__device__ volatile int g_stat[512];
__device__ int g_aggv[512];
__device__ int g_prefv[512];
__device__ int g_done;

__device__ __forceinline__ uint32_t smem_u32(const void* p) {
    uint32_t a;
    asm("{ .reg .u64 t; cvta.to.shared.u64 t, %1; cvt.u32.u64 %0, t; }" : "=r"(a) : "l"(p));
    return a;
}
__device__ __forceinline__ void cp16(uint32_t dst, const void* src) {
    asm volatile("cp.async.ca.shared.global [%0], [%1], 16;" :: "r"(dst), "l"(src));
}
#define CP_COMMIT() asm volatile("cp.async.commit_group;" ::: "memory")
#define CP_WAIT(N)  asm volatile("cp.async.wait_group %0;" :: "n"(N) : "memory")

__device__ __forceinline__ float lrelu(float x) { return x > 0.f ? x : 0.2f * x; }

// ============ 1) hist + (blocks 0-7) wal/war/Bt prep ============
__global__ void k_hist_prep(const int* __restrict__ isrc, const int* __restrict__ idst,
                            const int* __restrict__ xsrc, const int* __restrict__ xdst,
                            const float* __restrict__ W, const float* __restrict__ al,
                            const float* __restrict__ ar, const float* __restrict__ lam,
                            int n, int E) {
    int bid = blockIdx.x, tid = threadIdx.x;
    if (bid < 8) {
        int r = bid;
        if (tid < 128) {
            const float* Wr  = W + r * DD * DD + tid * DD;
            const float* alr = al + r * DD;
            const float* arr = ar + r * DD;
            float sl = 0.f, sr = 0.f;
            #pragma unroll 8
            for (int j = 0; j < DD; j++) { float w = Wr[j]; sl += w * alr[j]; sr += w * arr[j]; }
            g_wal[r * DD + tid] = sl;
            g_war[r * DD + tid] = sr;
        }
        float lr = lam[r >> 1];
        for (int i = tid; i < DD * DD; i += 256) {
            int nn = i >> 7, kk = i & 127;
            g_Bt[r * DD * DD + i] = __float2half_rn(lr * W[(r * DD + kk) * DD + nn]);
        }
    }
    int t = bid * 256 + tid;
    if (t >= 4 * E) return;
    int s = t / E, e = t - s * E;
    int key = (s == 0) ? idst[e] : (s == 1) ? xdst[e] : (s == 2) ? isrc[e] : xsrc[e];
    atomicAdd(&g_cnt[s * n + key], 1);
}

// ============ 2) merged: decoupled-lookback scan + elr (endpoint-packed) ============
__global__ void __launch_bounds__(1024) k_scan_elr(
    const float* __restrict__ fsrc, const float* __restrict__ fdst,
    int n, int len, int nbScan) {
    __shared__ int sm[1024];
    __shared__ int s_pref;
    __shared__ float4 swal[8 * 32], swar[8 * 32];
    int bid = blockIdx.x, tid = threadIdx.x;

    if (bid < nbScan) {
        int b = bid;
        int i = b * 1024 + tid;
        int v = (i < len) ? g_cnt[i] : 0;
        sm[tid] = v;
        __syncthreads();
        for (int off = 1; off < 1024; off <<= 1) {
            int t = (tid >= off) ? sm[tid - off] : 0;
            __syncthreads();
            sm[tid] += t;
            __syncthreads();
        }
        int incl = sm[tid];
        if (tid == 1023) {
            int total = incl;
            if (b == 0) {
                g_prefv[0] = total;
                __threadfence();
                g_stat[0] = 2;
                s_pref = 0;
            } else {
                g_aggv[b] = total;
                __threadfence();
                g_stat[b] = 1;
                int pref = 0;
                for (int j = b - 1; j >= 0;) {
                    int st;
                    do { st = g_stat[j]; } while (st == 0);
                    __threadfence();
                    if (st == 2) { pref += g_prefv[j]; break; }
                    pref += g_aggv[j]; j--;
                }
                g_prefv[b] = pref + total;
                __threadfence();
                g_stat[b] = 2;
                s_pref = pref;
            }
        }
        __syncthreads();
        int pref = s_pref;
        if (i < len) {
            int excl = incl - v + pref;
            g_rowptr[i] = excl;
            g_cursor[i] = excl;
            g_cnt[i] = 0;
        }
        __syncthreads();
        if (tid == 0) {
            int d = atomicAdd(&g_done, 1);
            if (d == nbScan - 1) {
                for (int j = 0; j < nbScan; j++) g_stat[j] = 0;
                g_done = 0;
                __threadfence();
            }
        }
        return;
    }

    // ---- elr + fp16 mirror (32 nodes per 1024-thread block) ----
    if (tid < 256) {
        swal[tid] = ((const float4*)g_wal)[tid];
        swar[tid] = ((const float4*)g_war)[tid];
    }
    __syncthreads();
    int warp = tid >> 5, lane = tid & 31;
    int node = (bid - nbScan) * 32 + warp;
    if (node >= n) return;
    float4 fs = ((const float4*)fsrc)[(long)node * 32 + lane];
    float4 fd = ((const float4*)fdst)[(long)node * 32 + lane];
    {
        __half2 a0 = __floats2half2_rn(fs.x, fs.y);
        __half2 a1 = __floats2half2_rn(fs.z, fs.w);
        __half2 b0 = __floats2half2_rn(fd.x, fd.y);
        __half2 b1 = __floats2half2_rn(fd.z, fd.w);
        uint2 ua, ub;
        ua.x = *reinterpret_cast<uint32_t*>(&a0); ua.y = *reinterpret_cast<uint32_t*>(&a1);
        ub.x = *reinterpret_cast<uint32_t*>(&b0); ub.y = *reinterpret_cast<uint32_t*>(&b1);
        ((uint2*)g_fI)[((long)node << 6) + lane] = ua;
        ((uint2*)g_fI)[((long)node << 6) + 32 + lane] = ub;
    }
    float p[16];
    #pragma unroll
    for (int r = 0; r < 8; r++) {
        float4 wl = swal[r * 32 + lane];
        float4 wr = swar[r * 32 + lane];
        bool useSrc = (r == 0 || r == 1 || r == 4 || r == 5);
        float4 x = useSrc ? fs : fd;
        p[r]     = x.x * wl.x + x.y * wl.y + x.z * wl.z + x.w * wl.w;
        p[8 + r] = fd.x * wr.x + fd.y * wr.y + fd.z * wr.z + fd.w * wr.w;
    }
    #pragma unroll
    for (int i = 0; i < 16; i++)
        #pragma unroll
        for (int o = 16; o; o >>= 1) p[i] += __shfl_xor_sync(0xffffffffu, p[i], o);
    if (lane == 0) {
        g_P[node]              = make_float4(p[0], p[2], p[12], p[14]);
        g_Q[node]              = make_float4(p[8], p[10], p[4],  p[6]);
        g_P[(long)MAXN + node] = make_float4(p[1], p[3], p[13], p[15]);
        g_Q[(long)MAXN + node] = make_float4(p[9], p[11], p[5],  p[7]);
    }
}

// ============ 3) fill + weights: one thread per physical edge (fwd + rev together) ============
__global__ void k_fill_w(const int* __restrict__ isrc, const int* __restrict__ idst,
                         const int* __restrict__ xsrc, const int* __restrict__ xdst,
                         int n, int E) {
    int t = blockIdx.x * blockDim.x + threadIdx.x;
    if (t >= 2 * E) return;
    int p = (t >= E) ? 1 : 0;
    int e = t - p * E;
    int src = p ? __ldg(&xsrc[e]) : __ldg(&isrc[e]);
    int dst = p ? __ldg(&xdst[e]) : __ldg(&idst[e]);
    float4 Ps = __ldg(&g_P[(long)p * MAXN + src]);
    float4 Qd = __ldg(&g_Q[(long)p * MAXN + dst]);
    long pn = (long)p * n;
    {
        int pos = atomicAdd(&g_cursor[pn + dst], 1);
        g_col[pos] = src;
        __half2 hw = __floats2half2_rn(__expf(lrelu(Ps.x + Qd.x)),
                                       __expf(lrelu(Ps.y + Qd.y)));
        g_w[pos] = *reinterpret_cast<unsigned*>(&hw);
    }
    {
        int pos = atomicAdd(&g_cursor[pn + 2L * n + src], 1);
        g_col[pos] = dst;
        __half2 hw = __floats2half2_rn(__expf(lrelu(Qd.z + Ps.z)),
                                       __expf(lrelu(Qd.w + Ps.w)));
        g_w[pos] = *reinterpret_cast<unsigned*>(&hw);
    }
}

// ============ 4) gather agg: fp16 HFMA2 accumulation, 8 nodes/block ============
__global__ void __launch_bounds__(256) k_agg(int n, int E) {
    int s = blockIdx.y;
    int warp = threadIdx.x >> 5, lane = threadIdx.x & 31;
    int node = blockIdx.x * 8 + warp;
    if (node >= n) return;
    int ra = (s < 2) ? s : s + 2;
    int rb = ra + 2;
    long idx = (long)s * n + node;
    int start = g_rowptr[idx];
    int end   = (idx + 1 < 4L * n) ? g_rowptr[idx + 1] : 4 * E;

    __half2 acc0 = __float2half2_rn(0.f), acc1 = acc0, acc2 = acc0, acc3 = acc0;
    float dena = 0.f, denb = 0.f;

    const char* fbase = (const char*)g_fI;
    unsigned laneByte = (unsigned)lane * 16u;
    bool loSide = lane < 16;

    for (int base = start; base < end; base += 32) {
        int k = base + lane;
        unsigned off = 0, wpack = 0;
        if (k < end) {
            int c = __ldg(&g_col[k]);
            wpack  = __ldg(&g_w[k]);
            off = (unsigned)c << 9;
        }
        {
            __half2 hw = *reinterpret_cast<__half2*>(&wpack);
            float2 wf = __half22float2(hw);
            dena += wf.x; denb += wf.y;
        }
        int num = min(32, end - base);
        int j = 0;
        for (; j + 3 < num; j += 4) {
            unsigned o[4], wp[4];
            #pragma unroll
            for (int u = 0; u < 4; u++) {
                o[u]  = __shfl_sync(0xffffffffu, off,   j + u);
                wp[u] = __shfl_sync(0xffffffffu, wpack, j + u);
            }
            uint4 v[4];
            #pragma unroll
            for (int u = 0; u < 4; u++)
                v[u] = __ldg((const uint4*)(fbase + (o[u] + laneByte)));
            #pragma unroll
            for (int u = 0; u < 4; u++) {
                unsigned hbits = loSide ? (wp[u] & 0xffffu) : (wp[u] >> 16);
                __half2 wh = __half2half2(*reinterpret_cast<__half*>(&hbits));
                acc0 = __hfma2(*reinterpret_cast<__half2*>(&v[u].x), wh, acc0);
                acc1 = __hfma2(*reinterpret_cast<__half2*>(&v[u].y), wh, acc1);
                acc2 = __hfma2(*reinterpret_cast<__half2*>(&v[u].z), wh, acc2);
                acc3 = __hfma2(*reinterpret_cast<__half2*>(&v[u].w), wh, acc3);
            }
        }
        for (; j < num; j++) {
            unsigned o  = __shfl_sync(0xffffffffu, off,   j);
            unsigned wp = __shfl_sync(0xffffffffu, wpack, j);
            unsigned hbits = loSide ? (wp & 0xffffu) : (wp >> 16);
            __half2 wh = __half2half2(*reinterpret_cast<__half*>(&hbits));
            uint4 v = __ldg((const uint4*)(fbase + (o + laneByte)));
            acc0 = __hfma2(*reinterpret_cast<__half2*>(&v.x), wh, acc0);
            acc1 = __hfma2(*reinterpret_cast<__half2*>(&v.y), wh, acc1);
            acc2 = __hfma2(*reinterpret_cast<__half2*>(&v.z), wh, acc2);
            acc3 = __hfma2(*reinterpret_cast<__half2*>(&v.w), wh, acc3);
        }
    }
    #pragma unroll
    for (int o = 16; o; o >>= 1) {
        dena += __shfl_xor_sync(0xffffffffu, dena, o);
        denb += __shfl_xor_sync(0xffffffffu, denb, o);
    }
    float den = loSide ? dena : denb;
    float inv = (den > 0.f) ? (1.0f / den) : 0.f;   // empty row -> 0 (no inf*0)
    __half2 hinv = __float2half2_rn(inv);
    acc0 = __hmul2(acc0, hinv);
    acc1 = __hmul2(acc1, hinv);
    acc2 = __hmul2(acc2, hinv);
    acc3 = __hmul2(acc3, hinv);
    uint4 val;
    val.x = *reinterpret_cast<uint32_t*>(&acc0);
    val.y = *reinterpret_cast<uint32_t*>(&acc1);
    val.z = *reinterpret_cast<uint32_t*>(&acc2);
    val.w = *reinterpret_cast<uint32_t*>(&acc3);
    int row = loSide ? ra : rb;
    int lo = lane & 15;
    uint4* dst = (uint4*)((char*)g_Y + ((long)row * NPAD + node) * 256) + lo;
    __stcs(dst, val);
}

// ============ 5) mma.sync fp16 fused GEMM, cp.async double-buffered ============
#define AS_OFF 0
#define BS_OFF 36864
#define BC_OFF 73728
#define GEMM_SMEM_BYTES (73728 + 512)
#define BUFB 18432

__device__ __forceinline__ void mma_f16(float* c, const uint32_t* a, const uint32_t* b) {
    asm volatile(
        "mma.sync.aligned.m16n8k16.row.col.f32.f16.f16.f32 "
        "{%0,%1,%2,%3}, {%4,%5,%6,%7}, {%8,%9}, {%0,%1,%2,%3};"
        : "+f"(c[0]), "+f"(c[1]), "+f"(c[2]), "+f"(c[3])
        : "r"(a[0]), "r"(a[1]), "r"(a[2]), "r"(a[3]), "r"(b[0]), "r"(b[1]));
}

__global__ void __launch_bounds__(256, 2) k_gemm_mma(
    const float* __restrict__ lam, const float* __restrict__ bias,
    const float* __restrict__ fdst, float* __restrict__ out, int n) {
    extern __shared__ char smc[];
    float* bcs = (float*)(smc + BC_OFF);
    uint32_t sm_base = smem_u32(smc);

    int tid = threadIdx.x, wid = tid >> 5, lane = tid & 31;
    int wm = wid & 1, wn = wid >> 1;
    int row0 = blockIdx.x * 128;
    int g = lane >> 2, q = lane & 3;

    if (tid < 128) {
        float s = 0.f;
        #pragma unroll
        for (int t = 0; t < 4; t++)
            s += lam[t] * (bias[(2 * t) * DD + tid] + bias[(2 * t + 1) * DD + tid]);
        bcs[tid] = s;
    }

    float acc[4][4][4];
    #pragma unroll
    for (int i = 0; i < 4; i++)
        #pragma unroll
        for (int j = 0; j < 4; j++)
            #pragma unroll
            for (int t = 0; t < 4; t++) acc[i][j][t] = 0.f;

    int lrow = tid >> 1;
    int lseg = (tid & 1) * 64;

    auto issue = [&](int c, int buf) {
        int r = c >> 1;
        int koff = (c & 1) * 128;
        const char* ys = (const char*)g_Y + ((long)r * NPAD + row0 + lrow) * 256 + koff + lseg;
        const char* bs = (const char*)g_Bt + ((long)r * DD + lrow) * 256 + koff + lseg;
        uint32_t ad = sm_base + AS_OFF + (uint32_t)buf * BUFB + (uint32_t)lrow * 144 + lseg;
        uint32_t bd = sm_base + BS_OFF + (uint32_t)buf * BUFB + (uint32_t)lrow * 144 + lseg;
        #pragma unroll
        for (int i = 0; i < 4; i++) {
            cp16(ad + i * 16, ys + i * 16);
            cp16(bd + i * 16, bs + i * 16);
        }
        CP_COMMIT();
    };

    issue(0, 0);
    #pragma unroll 1
    for (int c = 0; c < 16; c++) {
        int buf = c & 1;
        if (c < 15) { issue(c + 1, buf ^ 1); CP_WAIT(1); }
        else        { CP_WAIT(0); }
        __syncthreads();
        const char* Ab = smc + AS_OFF + buf * BUFB;
        const char* Bb = smc + BS_OFF + buf * BUFB;
        #pragma unroll
        for (int ks = 0; ks < 4; ks++) {
            int kbyte = (ks * 16 + 2 * q) * 2;
            uint32_t a[4][4], b[4][2];
            #pragma unroll
            for (int mf = 0; mf < 4; mf++) {
                int m = wm * 64 + mf * 16;
                const char* p0 = Ab + (m + g) * 144 + kbyte;
                const char* p1 = Ab + (m + g + 8) * 144 + kbyte;
                a[mf][0] = *(const uint32_t*)p0;
                a[mf][1] = *(const uint32_t*)p1;
                a[mf][2] = *(const uint32_t*)(p0 + 16);
                a[mf][3] = *(const uint32_t*)(p1 + 16);
            }
            #pragma unroll
            for (int nf = 0; nf < 4; nf++) {
                int nn = wn * 32 + nf * 8 + g;
                const char* p = Bb + nn * 144 + kbyte;
                b[nf][0] = *(const uint32_t*)p;
                b[nf][1] = *(const uint32_t*)(p + 16);
            }
            #pragma unroll
            for (int mf = 0; mf < 4; mf++)
                #pragma unroll
                for (int nf = 0; nf < 4; nf++)
                    mma_f16(acc[mf][nf], a[mf], b[nf]);
        }
        __syncthreads();
    }

    float cdst = 2.0f * (__ldg(&lam[0]) + __ldg(&lam[1]) + __ldg(&lam[2]) + __ldg(&lam[3]));
    float2* out2 = (float2*)out;
    const float2* fd2 = (const float2*)fdst;
    #pragma unroll
    for (int mf = 0; mf < 4; mf++) {
        #pragma unroll
        for (int half = 0; half < 2; half++) {
            int row = row0 + wm * 64 + mf * 16 + g + half * 8;
            if (row >= n) continue;
            #pragma unroll
            for (int nf = 0; nf < 4; nf++) {
                int col = wn * 32 + nf * 8 + 2 * q;
                float2 fd = fd2[(long)row * 64 + (col >> 1)];
                float c0 = acc[mf][nf][half * 2 + 0];
                float c1 = acc[mf][nf][half * 2 + 1];
                float2 o;
                o.x = c0 + cdst * fd.x + bcs[col];
                o.y = c1 + cdst * fd.y + bcs[col + 1];
                out2[(long)row * 64 + (col >> 1)] = o;
            }
        }
    }
}

extern "C" void kernel_launch(void* const* d_in, const int* in_sizes, int n_in,
                              void* d_out, int out_size) {
    const float* fsrc = (const float*)d_in[0];
    const float* fdst = (const float*)d_in[1];
    const int*   isrc = (const int*)d_in[2];
    const int*   idst = (const int*)d_in[3];
    const int*   xsrc = (const int*)d_in[4];
    const int*   xdst = (const int*)d_in[5];
    const float* W    = (const float*)d_in[6];
    const float* al   = (const float*)d_in[7];
    const float* ar   = (const float*)d_in[8];
    const float* bias = (const float*)d_in[9];
    const float* lam  = (const float*)d_in[10];
    float* out = (float*)d_out;

    int n = in_sizes[0] / DD;
    int E = in_sizes[2];
    int len = 4 * n;
    int nbScan = (len + 1023) / 1024;
    int histB = (4 * E + 255) / 256;
    int fillB = (2 * E + 255) / 256;
    int elrB1024 = (n + 31) / 32;

    static int configured = 0;
    if (!configured) {
        cudaFuncSetAttribute(k_gemm_mma, cudaFuncAttributeMaxDynamicSharedMemorySize,
                             GEMM_SMEM_BYTES);
        configured = 1;
    }

    k_hist_prep<<<histB, 256>>>(isrc, idst, xsrc, xdst, W, al, ar, lam, n, E);
    k_scan_elr<<<nbScan + elrB1024, 1024>>>(fsrc, fdst, n, len, nbScan);
    k_fill_w<<<fillB, 256>>>(isrc, idst, xsrc, xdst, n, E);
    k_agg<<<dim3((n + 7) / 8, 4), 256>>>(n, E);
    k_gemm_mma<<<(n + 127) / 128, 256, GEMM_SMEM_BYTES>>>(lam, bias, fdst, out, n);
}

// round 14
// speedup vs baseline: 1.0358x; 1.0358x over previous
#include <cuda_runtime.h>
#include <cuda_bf16.h>
#include <cuda_fp16.h>
#include <math.h>
#include <stdint.h>

#define MAXN 100000
#define NPAD 100096
#define MAXE 600000
#define DD 128

// ---------------- static device scratch (zero-initialized at load) ----------------
__device__ __align__(256) __half g_Y[8L * NPAD * DD];   // Y_r = S_r X_r (fp16)
__device__ __align__(256) __half g_Bt[8 * DD * DD];     // fp16(lam * W^T)
__device__ __align__(256) __half g_fI[MAXN * 2 * DD];   // node: 256B fsrc | 256B fdst (fp16)
__device__ float4 g_P[2 * MAXN];   // src-side: (el_f.ra, el_f.rb, er_r.ra, er_r.rb)
__device__ float4 g_Q[2 * MAXN];   // dst-side: (er_f.ra, er_f.rb, el_r.ra, el_r.rb)
__device__ float g_wal[8 * DD];
__device__ float g_war[8 * DD];
__device__ int   g_cnt[4 * MAXN];     // zeroed at load; re-zeroed by scan each run
__device__ int   g_rowptr[4 * MAXN];
__device__ int   g_cursor[4 * MAXN];
__device__ int   g_col[4 * MAXE];
__device__ unsigned g_w[4 * MAXE];    // per-slot half2(wa, wb)
// decoupled-lookback state (reset by last scan block each run)
__device__ volatile int g_stat[512];
__device__ int g_aggv[512];
__device__ int g_prefv[512];
__device__ int g_done;

__device__ __forceinline__ uint32_t smem_u32(const void* p) {
    uint32_t a;
    asm("{ .reg .u64 t; cvta.to.shared.u64 t, %1; cvt.u32.u64 %0, t; }" : "=r"(a) : "l"(p));
    return a;
}
__device__ __forceinline__ void cp16(uint32_t dst, const void* src) {
    asm volatile("cp.async.ca.shared.global [%0], [%1], 16;" :: "r"(dst), "l"(src));
}
#define CP_COMMIT() asm volatile("cp.async.commit_group;" ::: "memory")
#define CP_WAIT(N)  asm volatile("cp.async.wait_group %0;" :: "n"(N) : "memory")

__device__ __forceinline__ float lrelu(float x) { return x > 0.f ? x : 0.2f * x; }

// ============ 1) hist + (blocks 0-7) wal/war/Bt prep ============
__global__ void k_hist_prep(const int* __restrict__ isrc, const int* __restrict__ idst,
                            const int* __restrict__ xsrc, const int* __restrict__ xdst,
                            const float* __restrict__ W, const float* __restrict__ al,
                            const float* __restrict__ ar, const float* __restrict__ lam,
                            int n, int E) {
    int bid = blockIdx.x, tid = threadIdx.x;
    if (bid < 8) {
        int r = bid;
        if (tid < 128) {
            const float* Wr  = W + r * DD * DD + tid * DD;
            const float* alr = al + r * DD;
            const float* arr = ar + r * DD;
            float sl = 0.f, sr = 0.f;
            #pragma unroll 8
            for (int j = 0; j < DD; j++) { float w = Wr[j]; sl += w * alr[j]; sr += w * arr[j]; }
            g_wal[r * DD + tid] = sl;
            g_war[r * DD + tid] = sr;
        }
        float lr = lam[r >> 1];
        for (int i = tid; i < DD * DD; i += 256) {
            int nn = i >> 7, kk = i & 127;
            g_Bt[r * DD * DD + i] = __float2half_rn(lr * W[(r * DD + kk) * DD + nn]);
        }
    }
    int t = bid * 256 + tid;
    if (t >= 4 * E) return;
    int s = t / E, e = t - s * E;
    int key = (s == 0) ? idst[e] : (s == 1) ? xdst[e] : (s == 2) ? isrc[e] : xsrc[e];
    atomicAdd(&g_cnt[s * n + key], 1);
}

// ============ 2) merged: decoupled-lookback scan + elr (endpoint-packed) ============
__global__ void __launch_bounds__(1024) k_scan_elr(
    const float* __restrict__ fsrc, const float* __restrict__ fdst,
    int n, int len, int nbScan) {
    __shared__ int sm[1024];
    __shared__ int s_pref;
    __shared__ float4 swal[8 * 32], swar[8 * 32];
    int bid = blockIdx.x, tid = threadIdx.x;

    if (bid < nbScan) {
        int b = bid;
        int i = b * 1024 + tid;
        int v = (i < len) ? g_cnt[i] : 0;
        sm[tid] = v;
        __syncthreads();
        for (int off = 1; off < 1024; off <<= 1) {
            int t = (tid >= off) ? sm[tid - off] : 0;
            __syncthreads();
            sm[tid] += t;
            __syncthreads();
        }
        int incl = sm[tid];
        if (tid == 1023) {
            int total = incl;
            if (b == 0) {
                g_prefv[0] = total;
                __threadfence();
                g_stat[0] = 2;
                s_pref = 0;
            } else {
                g_aggv[b] = total;
                __threadfence();
                g_stat[b] = 1;
                int pref = 0;
                for (int j = b - 1; j >= 0;) {
                    int st;
                    do { st = g_stat[j]; } while (st == 0);
                    __threadfence();
                    if (st == 2) { pref += g_prefv[j]; break; }
                    pref += g_aggv[j]; j--;
                }
                g_prefv[b] = pref + total;
                __threadfence();
                g_stat[b] = 2;
                s_pref = pref;
            }
        }
        __syncthreads();
        int pref = s_pref;
        if (i < len) {
            int excl = incl - v + pref;
            g_rowptr[i] = excl;
            g_cursor[i] = excl;
            g_cnt[i] = 0;
        }
        __syncthreads();
        if (tid == 0) {
            int d = atomicAdd(&g_done, 1);
            if (d == nbScan - 1) {
                for (int j = 0; j < nbScan; j++) g_stat[j] = 0;
                g_done = 0;
                __threadfence();
            }
        }
        return;
    }

    // ---- elr + fp16 mirror (32 nodes per 1024-thread block) ----
    if (tid < 256) {
        swal[tid] = ((const float4*)g_wal)[tid];
        swar[tid] = ((const float4*)g_war)[tid];
    }
    __syncthreads();
    int warp = tid >> 5, lane = tid & 31;
    int node = (bid - nbScan) * 32 + warp;
    if (node >= n) return;
    float4 fs = ((const float4*)fsrc)[(long)node * 32 + lane];
    float4 fd = ((const float4*)fdst)[(long)node * 32 + lane];
    {
        __half2 a0 = __floats2half2_rn(fs.x, fs.y);
        __half2 a1 = __floats2half2_rn(fs.z, fs.w);
        __half2 b0 = __floats2half2_rn(fd.x, fd.y);
        __half2 b1 = __floats2half2_rn(fd.z, fd.w);
        uint2 ua, ub;
        ua.x = *reinterpret_cast<uint32_t*>(&a0); ua.y = *reinterpret_cast<uint32_t*>(&a1);
        ub.x = *reinterpret_cast<uint32_t*>(&b0); ub.y = *reinterpret_cast<uint32_t*>(&b1);
        ((uint2*)g_fI)[((long)node << 6) + lane] = ua;
        ((uint2*)g_fI)[((long)node << 6) + 32 + lane] = ub;
    }
    float p[16];
    #pragma unroll
    for (int r = 0; r < 8; r++) {
        float4 wl = swal[r * 32 + lane];
        float4 wr = swar[r * 32 + lane];
        bool useSrc = (r == 0 || r == 1 || r == 4 || r == 5);
        float4 x = useSrc ? fs : fd;
        p[r]     = x.x * wl.x + x.y * wl.y + x.z * wl.z + x.w * wl.w;
        p[8 + r] = fd.x * wr.x + fd.y * wr.y + fd.z * wr.z + fd.w * wr.w;
    }
    #pragma unroll
    for (int i = 0; i < 16; i++)
        #pragma unroll
        for (int o = 16; o; o >>= 1) p[i] += __shfl_xor_sync(0xffffffffu, p[i], o);
    if (lane == 0) {
        g_P[node]              = make_float4(p[0], p[2], p[12], p[14]);
        g_Q[node]              = make_float4(p[8], p[10], p[4],  p[6]);
        g_P[(long)MAXN + node] = make_float4(p[1], p[3], p[13], p[15]);
        g_Q[(long)MAXN + node] = make_float4(p[9], p[11], p[5],  p[7]);
    }
}

// ============ 3) fill + weights: one thread per physical edge (fwd + rev together) ============
__global__ void k_fill_w(const int* __restrict__ isrc, const int* __restrict__ idst,
                         const int* __restrict__ xsrc, const int* __restrict__ xdst,
                         int n, int E) {
    int t = blockIdx.x * blockDim.x + threadIdx.x;
    if (t >= 2 * E) return;
    int p = (t >= E) ? 1 : 0;
    int e = t - p * E;
    int src = p ? __ldg(&xsrc[e]) : __ldg(&isrc[e]);
    int dst = p ? __ldg(&xdst[e]) : __ldg(&idst[e]);
    float4 Ps = __ldg(&g_P[(long)p * MAXN + src]);
    float4 Qd = __ldg(&g_Q[(long)p * MAXN + dst]);
    long pn = (long)p * n;
    {
        int pos = atomicAdd(&g_cursor[pn + dst], 1);
        g_col[pos] = src;
        __half2 hw = __floats2half2_rn(__expf(lrelu(Ps.x + Qd.x)),
                                       __expf(lrelu(Ps.y + Qd.y)));
        g_w[pos] = *reinterpret_cast<unsigned*>(&hw);
    }
    {
        int pos = atomicAdd(&g_cursor[pn + 2L * n + src], 1);
        g_col[pos] = dst;
        __half2 hw = __floats2half2_rn(__expf(lrelu(Qd.z + Ps.z)),
                                       __expf(lrelu(Qd.w + Ps.w)));
        g_w[pos] = *reinterpret_cast<unsigned*>(&hw);
    }
}

// ============ 4) gather agg: fp16 HFMA2 accumulation, 8 nodes/block ============
__global__ void __launch_bounds__(256) k_agg(int n, int E) {
    int s = blockIdx.y;
    int warp = threadIdx.x >> 5, lane = threadIdx.x & 31;
    int node = blockIdx.x * 8 + warp;
    if (node >= n) return;
    int ra = (s < 2) ? s : s + 2;
    int rb = ra + 2;
    long idx = (long)s * n + node;
    int start = g_rowptr[idx];
    int end   = (idx + 1 < 4L * n) ? g_rowptr[idx + 1] : 4 * E;

    __half2 acc0 = __float2half2_rn(0.f), acc1 = acc0, acc2 = acc0, acc3 = acc0;
    float dena = 0.f, denb = 0.f;

    const char* fbase = (const char*)g_fI;
    unsigned laneByte = (unsigned)lane * 16u;
    bool loSide = lane < 16;

    for (int base = start; base < end; base += 32) {
        int k = base + lane;
        unsigned off = 0, wpack = 0;
        if (k < end) {
            int c = __ldg(&g_col[k]);
            wpack  = __ldg(&g_w[k]);
            off = (unsigned)c << 9;
        }
        {
            __half2 hw = *reinterpret_cast<__half2*>(&wpack);
            float2 wf = __half22float2(hw);
            dena += wf.x; denb += wf.y;
        }
        int num = min(32, end - base);
        int j = 0;
        for (; j + 3 < num; j += 4) {
            unsigned o[4], wp[4];
            #pragma unroll
            for (int u = 0; u < 4; u++) {
                o[u]  = __shfl_sync(0xffffffffu, off,   j + u);
                wp[u] = __shfl_sync(0xffffffffu, wpack, j + u);
            }
            uint4 v[4];
            #pragma unroll
            for (int u = 0; u < 4; u++)
                v[u] = __ldg((const uint4*)(fbase + (o[u] + laneByte)));
            #pragma unroll
            for (int u = 0; u < 4; u++) {
                unsigned hbits = loSide ? (wp[u] & 0xffffu) : (wp[u] >> 16);
                __half2 wh = __half2half2(*reinterpret_cast<__half*>(&hbits));
                acc0 = __hfma2(*reinterpret_cast<__half2*>(&v[u].x), wh, acc0);
                acc1 = __hfma2(*reinterpret_cast<__half2*>(&v[u].y), wh, acc1);
                acc2 = __hfma2(*reinterpret_cast<__half2*>(&v[u].z), wh, acc2);
                acc3 = __hfma2(*reinterpret_cast<__half2*>(&v[u].w), wh, acc3);
            }
        }
        for (; j < num; j++) {
            unsigned o  = __shfl_sync(0xffffffffu, off,   j);
            unsigned wp = __shfl_sync(0xffffffffu, wpack, j);
            unsigned hbits = loSide ? (wp & 0xffffu) : (wp >> 16);
            __half2 wh = __half2half2(*reinterpret_cast<__half*>(&hbits));
            uint4 v = __ldg((const uint4*)(fbase + (o + laneByte)));
            acc0 = __hfma2(*reinterpret_cast<__half2*>(&v.x), wh, acc0);
            acc1 = __hfma2(*reinterpret_cast<__half2*>(&v.y), wh, acc1);
            acc2 = __hfma2(*reinterpret_cast<__half2*>(&v.z), wh, acc2);
            acc3 = __hfma2(*reinterpret_cast<__half2*>(&v.w), wh, acc3);
        }
    }
    #pragma unroll
    for (int o = 16; o; o >>= 1) {
        dena += __shfl_xor_sync(0xffffffffu, dena, o);
        denb += __shfl_xor_sync(0xffffffffu, denb, o);
    }
    float den = loSide ? dena : denb;
    float inv = (den > 0.f) ? (1.0f / den) : 0.f;
    __half2 hinv = __float2half2_rn(inv);
    acc0 = __hmul2(acc0, hinv);
    acc1 = __hmul2(acc1, hinv);
    acc2 = __hmul2(acc2, hinv);
    acc3 = __hmul2(acc3, hinv);
    uint4 val;
    val.x = *reinterpret_cast<uint32_t*>(&acc0);
    val.y = *reinterpret_cast<uint32_t*>(&acc1);
    val.z = *reinterpret_cast<uint32_t*>(&acc2);
    val.w = *reinterpret_cast<uint32_t*>(&acc3);
    int row = loSide ? ra : rb;
    int lo = lane & 15;
    uint4* dst = (uint4*)((char*)g_Y + ((long)row * NPAD + node) * 256) + lo;
    __stcs(dst, val);
}

// ============ 5) mma.sync fp16 GEMM, cp.async double-buffered, ldmatrix frags ============
#define AS_OFF 0
#define BS_OFF 36864
#define BC_OFF 73728
#define GEMM_SMEM_BYTES (73728 + 512)
#define BUFB 18432

__device__ __forceinline__ void mma_f16(float* c, const uint32_t* a, const uint32_t* b) {
    asm volatile(
        "mma.sync.aligned.m16n8k16.row.col.f32.f16.f16.f32 "
        "{%0,%1,%2,%3}, {%4,%5,%6,%7}, {%8,%9}, {%0,%1,%2,%3};"
        : "+f"(c[0]), "+f"(c[1]), "+f"(c[2]), "+f"(c[3])
        : "r"(a[0]), "r"(a[1]), "r"(a[2]), "r"(a[3]), "r"(b[0]), "r"(b[1]));
}
__device__ __forceinline__ void ldsm_x4(uint32_t* r, uint32_t addr) {
    asm volatile("ldmatrix.sync.aligned.m8n8.x4.shared.b16 {%0,%1,%2,%3}, [%4];"
                 : "=r"(r[0]), "=r"(r[1]), "=r"(r[2]), "=r"(r[3]) : "r"(addr));
}

__global__ void __launch_bounds__(256, 2) k_gemm_mma(
    const float* __restrict__ lam, const float* __restrict__ bias,
    const float* __restrict__ fdst, float* __restrict__ out, int n) {
    extern __shared__ char smc[];
    float* bcs = (float*)(smc + BC_OFF);
    uint32_t sm_base = smem_u32(smc);

    int tid = threadIdx.x, wid = tid >> 5, lane = tid & 31;
    int wm = wid & 1, wn = wid >> 1;
    int row0 = blockIdx.x * 128;
    int g = lane >> 2, q = lane & 3;

    if (tid < 128) {
        float s = 0.f;
        #pragma unroll
        for (int t = 0; t < 4; t++)
            s += lam[t] * (bias[(2 * t) * DD + tid] + bias[(2 * t + 1) * DD + tid]);
        bcs[tid] = s;
    }

    float acc[4][4][4];
    #pragma unroll
    for (int i = 0; i < 4; i++)
        #pragma unroll
        for (int j = 0; j < 4; j++)
            #pragma unroll
            for (int t = 0; t < 4; t++) acc[i][j][t] = 0.f;

    int lrow = tid >> 1;
    int lseg = (tid & 1) * 64;

    // ldmatrix per-lane offsets (bytes) within a tile base
    // A x4: lanes 0-7 tile(m+r,k0) | 8-15 (m+8+r,k0) | 16-23 (m+r,k8) | 24-31 (m+8+r,k8)
    uint32_t aLaneOff = (uint32_t)(((((lane >> 3) & 1) * 8) + (lane & 7)) * 144 + (lane >> 4) * 16);
    // B x4: lanes 0-7 (n+r,k0) | 8-15 (n+r,k8) | 16-23 (n+8+r,k0) | 24-31 (n+8+r,k8)
    uint32_t bLaneOff = (uint32_t)((((lane >> 4) * 8) + (lane & 7)) * 144 + ((lane >> 3) & 1) * 16);

    auto issue = [&](int c, int buf) {
        int r = c >> 1;
        int koff = (c & 1) * 128;
        const char* ys = (const char*)g_Y + ((long)r * NPAD + row0 + lrow) * 256 + koff + lseg;
        const char* bs = (const char*)g_Bt + ((long)r * DD + lrow) * 256 + koff + lseg;
        uint32_t ad = sm_base + AS_OFF + (uint32_t)buf * BUFB + (uint32_t)lrow * 144 + lseg;
        uint32_t bd = sm_base + BS_OFF + (uint32_t)buf * BUFB + (uint32_t)lrow * 144 + lseg;
        #pragma unroll
        for (int i = 0; i < 4; i++) {
            cp16(ad + i * 16, ys + i * 16);
            cp16(bd + i * 16, bs + i * 16);
        }
        CP_COMMIT();
    };

    issue(0, 0);
    #pragma unroll 1
    for (int c = 0; c < 16; c++) {
        int buf = c & 1;
        if (c < 15) { issue(c + 1, buf ^ 1); CP_WAIT(1); }
        else        { CP_WAIT(0); }
        __syncthreads();
        uint32_t Ab = sm_base + AS_OFF + (uint32_t)buf * BUFB;
        uint32_t Bb = sm_base + BS_OFF + (uint32_t)buf * BUFB;
        #pragma unroll
        for (int ks = 0; ks < 4; ks++) {
            uint32_t a[4][4], b[4][2];
            #pragma unroll
            for (int mf = 0; mf < 4; mf++) {
                uint32_t addr = Ab + (uint32_t)((wm * 64 + mf * 16) * 144 + ks * 32) + aLaneOff;
                ldsm_x4(a[mf], addr);
            }
            #pragma unroll
            for (int np = 0; np < 2; np++) {
                uint32_t r4[4];
                uint32_t addr = Bb + (uint32_t)((wn * 32 + np * 16) * 144 + ks * 32) + bLaneOff;
                ldsm_x4(r4, addr);
                b[np * 2][0] = r4[0]; b[np * 2][1] = r4[1];
                b[np * 2 + 1][0] = r4[2]; b[np * 2 + 1][1] = r4[3];
            }
            #pragma unroll
            for (int mf = 0; mf < 4; mf++)
                #pragma unroll
                for (int nf = 0; nf < 4; nf++)
                    mma_f16(acc[mf][nf], a[mf], b[nf]);
        }
        __syncthreads();
    }

    float cdst = 2.0f * (__ldg(&lam[0]) + __ldg(&lam[1]) + __ldg(&lam[2]) + __ldg(&lam[3]));
    float2* out2 = (float2*)out;
    const float2* fd2 = (const float2*)fdst;
    #pragma unroll
    for (int mf = 0; mf < 4; mf++) {
        #pragma unroll
        for (int half = 0; half < 2; half++) {
            int row = row0 + wm * 64 + mf * 16 + g + half * 8;
            if (row >= n) continue;
            #pragma unroll
            for (int nf = 0; nf < 4; nf++) {
                int col = wn * 32 + nf * 8 + 2 * q;
                float2 fd = fd2[(long)row * 64 + (col >> 1)];
                float c0 = acc[mf][nf][half * 2 + 0];
                float c1 = acc[mf][nf][half * 2 + 1];
                float2 o;
                o.x = c0 + cdst * fd.x + bcs[col];
                o.y = c1 + cdst * fd.y + bcs[col + 1];
                out2[(long)row * 64 + (col >> 1)] = o;
            }
        }
    }
}

extern "C" void kernel_launch(void* const* d_in, const int* in_sizes, int n_in,
                              void* d_out, int out_size) {
    const float* fsrc = (const float*)d_in[0];
    const float* fdst = (const float*)d_in[1];
    const int*   isrc = (const int*)d_in[2];
    const int*   idst = (const int*)d_in[3];
    const int*   xsrc = (const int*)d_in[4];
    const int*   xdst = (const int*)d_in[5];
    const float* W    = (const float*)d_in[6];
    const float* al   = (const float*)d_in[7];
    const float* ar   = (const float*)d_in[8];
    const float* bias = (const float*)d_in[9];
    const float* lam  = (const float*)d_in[10];
    float* out = (float*)d_out;

    int n = in_sizes[0] / DD;
    int E = in_sizes[2];
    int len = 4 * n;
    int nbScan = (len + 1023) / 1024;
    int histB = (4 * E + 255) / 256;
    int fillB = (2 * E + 255) / 256;
    int elrB1024 = (n + 31) / 32;

    static int configured = 0;
    if (!configured) {
        cudaFuncSetAttribute(k_gemm_mma, cudaFuncAttributeMaxDynamicSharedMemorySize,
                             GEMM_SMEM_BYTES);
        configured = 1;
    }

    k_hist_prep<<<histB, 256>>>(isrc, idst, xsrc, xdst, W, al, ar, lam, n, E);
    k_scan_elr<<<nbScan + elrB1024, 1024>>>(fsrc, fdst, n, len, nbScan);
    k_fill_w<<<fillB, 256>>>(isrc, idst, xsrc, xdst, n, E);
    k_agg<<<dim3((n + 7) / 8, 4), 256>>>(n, E);
    k_gemm_mma<<<(n + 127) / 128, 256, GEMM_SMEM_BYTES>>>(lam, bias, fdst, out, n);
}

// round 15
// speedup vs baseline: 1.0545x; 1.0180x over previous
#include <cuda_runtime.h>
#include <cuda_bf16.h>
#include <cuda_fp16.h>
#include <math.h>
#include <stdint.h>

#define MAXN 100000
#define NPAD 100096
#define MAXE 600000
#define DD 128

// ---------------- static device scratch (zero-initialized at load) ----------------
__device__ __align__(256) __half g_Y[8L * NPAD * DD];   // Y_r = S_r X_r (fp16)
__device__ __align__(256) __half g_Bt[8 * DD * DD];     // fp16(lam * W^T)
__device__ __align__(256) __half g_fI[MAXN * 2 * DD];   // node: 256B fsrc | 256B fdst (fp16)
__device__ float4 g_P[2 * MAXN];   // src-side: (el_f.ra, el_f.rb, er_r.ra, er_r.rb)
__device__ float4 g_Q[2 * MAXN];   // dst-side: (er_f.ra, er_f.rb, el_r.ra, el_r.rb)
__device__ float g_wal[8 * DD];
__device__ float g_war[8 * DD];
__device__ int   g_cnt[4 * MAXN];     // zeroed at load; re-zeroed by scan each run
__device__ int   g_rowptr[4 * MAXN];
__device__ int   g_cursor[4 * MAXN];
__device__ int   g_col[4 * MAXE];
__device__ unsigned g_w[4 * MAXE];    // per-slot half2(wa, wb)
// decoupled-lookback state (reset by last scan block each run)
__device__ volatile int g_stat[512];
__device__ int g_aggv[512];
__device__ int g_prefv[512];
__device__ int g_done;

__device__ __forceinline__ uint32_t smem_u32(const void* p) {
    uint32_t a;
    asm("{ .reg .u64 t; cvta.to.shared.u64 t, %1; cvt.u32.u64 %0, t; }" : "=r"(a) : "l"(p));
    return a;
}
__device__ __forceinline__ void cp16(uint32_t dst, const void* src) {
    asm volatile("cp.async.ca.shared.global [%0], [%1], 16;" :: "r"(dst), "l"(src));
}
#define CP_COMMIT() asm volatile("cp.async.commit_group;" ::: "memory")
#define CP_WAIT(N)  asm volatile("cp.async.wait_group %0;" :: "n"(N) : "memory")

__device__ __forceinline__ float lrelu(float x) { return x > 0.f ? x : 0.2f * x; }

// ============ 1) hist + (blocks 0-7) wal/war/Bt prep ============
__global__ void k_hist_prep(const int* __restrict__ isrc, const int* __restrict__ idst,
                            const int* __restrict__ xsrc, const int* __restrict__ xdst,
                            const float* __restrict__ W, const float* __restrict__ al,
                            const float* __restrict__ ar, const float* __restrict__ lam,
                            int n, int E) {
    int bid = blockIdx.x, tid = threadIdx.x;
    if (bid < 8) {
        int r = bid;
        if (tid < 128) {
            const float* Wr  = W + r * DD * DD + tid * DD;
            const float* alr = al + r * DD;
            const float* arr = ar + r * DD;
            float sl = 0.f, sr = 0.f;
            #pragma unroll 8
            for (int j = 0; j < DD; j++) { float w = Wr[j]; sl += w * alr[j]; sr += w * arr[j]; }
            g_wal[r * DD + tid] = sl;
            g_war[r * DD + tid] = sr;
        }
        float lr = lam[r >> 1];
        for (int i = tid; i < DD * DD; i += 256) {
            int nn = i >> 7, kk = i & 127;
            g_Bt[r * DD * DD + i] = __float2half_rn(lr * W[(r * DD + kk) * DD + nn]);
        }
    }
    int t = bid * 256 + tid;
    if (t >= 4 * E) return;
    int s = t / E, e = t - s * E;
    int key = (s == 0) ? idst[e] : (s == 1) ? xdst[e] : (s == 2) ? isrc[e] : xsrc[e];
    atomicAdd(&g_cnt[s * n + key], 1);
}

// ============ 2) merged: decoupled-lookback scan + elr (endpoint-packed) ============
__global__ void __launch_bounds__(1024) k_scan_elr(
    const float* __restrict__ fsrc, const float* __restrict__ fdst,
    int n, int len, int nbScan) {
    __shared__ int sm[1024];
    __shared__ int s_pref;
    __shared__ float4 swal[8 * 32], swar[8 * 32];
    int bid = blockIdx.x, tid = threadIdx.x;

    if (bid < nbScan) {
        int b = bid;
        int i = b * 1024 + tid;
        int v = (i < len) ? g_cnt[i] : 0;
        sm[tid] = v;
        __syncthreads();
        for (int off = 1; off < 1024; off <<= 1) {
            int t = (tid >= off) ? sm[tid - off] : 0;
            __syncthreads();
            sm[tid] += t;
            __syncthreads();
        }
        int incl = sm[tid];
        if (tid == 1023) {
            int total = incl;
            if (b == 0) {
                g_prefv[0] = total;
                __threadfence();
                g_stat[0] = 2;
                s_pref = 0;
            } else {
                g_aggv[b] = total;
                __threadfence();
                g_stat[b] = 1;
                int pref = 0;
                for (int j = b - 1; j >= 0;) {
                    int st;
                    do { st = g_stat[j]; } while (st == 0);
                    __threadfence();
                    if (st == 2) { pref += g_prefv[j]; break; }
                    pref += g_aggv[j]; j--;
                }
                g_prefv[b] = pref + total;
                __threadfence();
                g_stat[b] = 2;
                s_pref = pref;
            }
        }
        __syncthreads();
        int pref = s_pref;
        if (i < len) {
            int excl = incl - v + pref;
            g_rowptr[i] = excl;
            g_cursor[i] = excl;
            g_cnt[i] = 0;
        }
        __syncthreads();
        if (tid == 0) {
            int d = atomicAdd(&g_done, 1);
            if (d == nbScan - 1) {
                for (int j = 0; j < nbScan; j++) g_stat[j] = 0;
                g_done = 0;
                __threadfence();
            }
        }
        return;
    }

    // ---- elr + fp16 mirror (32 nodes per 1024-thread block) ----
    if (tid < 256) {
        swal[tid] = ((const float4*)g_wal)[tid];
        swar[tid] = ((const float4*)g_war)[tid];
    }
    __syncthreads();
    int warp = tid >> 5, lane = tid & 31;
    int node = (bid - nbScan) * 32 + warp;
    if (node >= n) return;
    float4 fs = ((const float4*)fsrc)[(long)node * 32 + lane];
    float4 fd = ((const float4*)fdst)[(long)node * 32 + lane];
    {
        __half2 a0 = __floats2half2_rn(fs.x, fs.y);
        __half2 a1 = __floats2half2_rn(fs.z, fs.w);
        __half2 b0 = __floats2half2_rn(fd.x, fd.y);
        __half2 b1 = __floats2half2_rn(fd.z, fd.w);
        uint2 ua, ub;
        ua.x = *reinterpret_cast<uint32_t*>(&a0); ua.y = *reinterpret_cast<uint32_t*>(&a1);
        ub.x = *reinterpret_cast<uint32_t*>(&b0); ub.y = *reinterpret_cast<uint32_t*>(&b1);
        ((uint2*)g_fI)[((long)node << 6) + lane] = ua;
        ((uint2*)g_fI)[((long)node << 6) + 32 + lane] = ub;
    }
    float p[16];
    #pragma unroll
    for (int r = 0; r < 8; r++) {
        float4 wl = swal[r * 32 + lane];
        float4 wr = swar[r * 32 + lane];
        bool useSrc = (r == 0 || r == 1 || r == 4 || r == 5);
        float4 x = useSrc ? fs : fd;
        p[r]     = x.x * wl.x + x.y * wl.y + x.z * wl.z + x.w * wl.w;
        p[8 + r] = fd.x * wr.x + fd.y * wr.y + fd.z * wr.z + fd.w * wr.w;
    }
    #pragma unroll
    for (int i = 0; i < 16; i++)
        #pragma unroll
        for (int o = 16; o; o >>= 1) p[i] += __shfl_xor_sync(0xffffffffu, p[i], o);
    if (lane == 0) {
        g_P[node]              = make_float4(p[0], p[2], p[12], p[14]);
        g_Q[node]              = make_float4(p[8], p[10], p[4],  p[6]);
        g_P[(long)MAXN + node] = make_float4(p[1], p[3], p[13], p[15]);
        g_Q[(long)MAXN + node] = make_float4(p[9], p[11], p[5],  p[7]);
    }
}

// ============ 3) fill + weights: one thread per physical edge (fwd + rev together) ============
__global__ void k_fill_w(const int* __restrict__ isrc, const int* __restrict__ idst,
                         const int* __restrict__ xsrc, const int* __restrict__ xdst,
                         int n, int E) {
    int t = blockIdx.x * blockDim.x + threadIdx.x;
    if (t >= 2 * E) return;
    int p = (t >= E) ? 1 : 0;
    int e = t - p * E;
    int src = p ? __ldg(&xsrc[e]) : __ldg(&isrc[e]);
    int dst = p ? __ldg(&xdst[e]) : __ldg(&idst[e]);
    float4 Ps = __ldg(&g_P[(long)p * MAXN + src]);
    float4 Qd = __ldg(&g_Q[(long)p * MAXN + dst]);
    long pn = (long)p * n;
    {
        int pos = atomicAdd(&g_cursor[pn + dst], 1);
        g_col[pos] = src;
        __half2 hw = __floats2half2_rn(__expf(lrelu(Ps.x + Qd.x)),
                                       __expf(lrelu(Ps.y + Qd.y)));
        g_w[pos] = *reinterpret_cast<unsigned*>(&hw);
    }
    {
        int pos = atomicAdd(&g_cursor[pn + 2L * n + src], 1);
        g_col[pos] = dst;
        __half2 hw = __floats2half2_rn(__expf(lrelu(Qd.z + Ps.z)),
                                       __expf(lrelu(Qd.w + Ps.w)));
        g_w[pos] = *reinterpret_cast<unsigned*>(&hw);
    }
}

// ============ 4) gather agg: 2 consecutive nodes per warp (double MLP) ============
__global__ void __launch_bounds__(256) k_agg(int n, int E) {
    int s = blockIdx.y;
    int warp = threadIdx.x >> 5, lane = threadIdx.x & 31;
    int node0 = blockIdx.x * 16 + warp * 2;
    if (node0 >= n) return;
    bool has1 = (node0 + 1) < n;
    int ra = (s < 2) ? s : s + 2;
    int rb = ra + 2;
    long idx = (long)s * n + node0;
    int start0 = g_rowptr[idx];
    int end0   = g_rowptr[idx + 1];          // node0+1 exists in structure s or is node1 row start
    int start1 = end0;
    int end1;
    if (has1) end1 = (idx + 2 < 4L * n) ? g_rowptr[idx + 2] : 4 * E;
    else      end1 = start1;
    // note: when node0 == n-1 in a structure, idx+1 row is the next structure's
    // first row only if node0+1>=n; here has1 guards that (end1=start1 -> no work).

    __half2 a00 = __float2half2_rn(0.f), a01 = a00, a02 = a00, a03 = a00;
    __half2 a10 = a00, a11 = a00, a12 = a00, a13 = a00;
    float den0a = 0.f, den0b = 0.f, den1a = 0.f, den1b = 0.f;

    const char* fbase = (const char*)g_fI;
    unsigned laneByte = (unsigned)lane * 16u;
    bool loSide = lane < 16;

    int base0 = start0, base1 = start1;
    while (base0 < end0 || base1 < end1) {
        unsigned off0 = 0, wp0 = 0, off1 = 0, wp1 = 0;
        if (base0 < end0) {
            int k = base0 + lane;
            if (k < end0) {
                int c = __ldg(&g_col[k]);
                wp0 = __ldg(&g_w[k]);
                off0 = (unsigned)c << 9;
            }
        }
        if (base1 < end1) {
            int k = base1 + lane;
            if (k < end1) {
                int c = __ldg(&g_col[k]);
                wp1 = __ldg(&g_w[k]);
                off1 = (unsigned)c << 9;
            }
        }
        {
            __half2 h0 = *reinterpret_cast<__half2*>(&wp0);
            float2 f0 = __half22float2(h0);
            den0a += f0.x; den0b += f0.y;
            __half2 h1 = *reinterpret_cast<__half2*>(&wp1);
            float2 f1 = __half22float2(h1);
            den1a += f1.x; den1b += f1.y;
        }
        if (base0 < end0) {
            int num = min(32, end0 - base0);
            int j = 0;
            for (; j + 3 < num; j += 4) {
                unsigned o[4], wp[4];
                #pragma unroll
                for (int u = 0; u < 4; u++) {
                    o[u]  = __shfl_sync(0xffffffffu, off0, j + u);
                    wp[u] = __shfl_sync(0xffffffffu, wp0,  j + u);
                }
                uint4 v[4];
                #pragma unroll
                for (int u = 0; u < 4; u++)
                    v[u] = __ldg((const uint4*)(fbase + (o[u] + laneByte)));
                #pragma unroll
                for (int u = 0; u < 4; u++) {
                    unsigned hb = loSide ? (wp[u] & 0xffffu) : (wp[u] >> 16);
                    __half2 wh = __half2half2(*reinterpret_cast<__half*>(&hb));
                    a00 = __hfma2(*reinterpret_cast<__half2*>(&v[u].x), wh, a00);
                    a01 = __hfma2(*reinterpret_cast<__half2*>(&v[u].y), wh, a01);
                    a02 = __hfma2(*reinterpret_cast<__half2*>(&v[u].z), wh, a02);
                    a03 = __hfma2(*reinterpret_cast<__half2*>(&v[u].w), wh, a03);
                }
            }
            for (; j < num; j++) {
                unsigned o  = __shfl_sync(0xffffffffu, off0, j);
                unsigned wp = __shfl_sync(0xffffffffu, wp0,  j);
                unsigned hb = loSide ? (wp & 0xffffu) : (wp >> 16);
                __half2 wh = __half2half2(*reinterpret_cast<__half*>(&hb));
                uint4 v = __ldg((const uint4*)(fbase + (o + laneByte)));
                a00 = __hfma2(*reinterpret_cast<__half2*>(&v.x), wh, a00);
                a01 = __hfma2(*reinterpret_cast<__half2*>(&v.y), wh, a01);
                a02 = __hfma2(*reinterpret_cast<__half2*>(&v.z), wh, a02);
                a03 = __hfma2(*reinterpret_cast<__half2*>(&v.w), wh, a03);
            }
        }
        if (base1 < end1) {
            int num = min(32, end1 - base1);
            int j = 0;
            for (; j + 3 < num; j += 4) {
                unsigned o[4], wp[4];
                #pragma unroll
                for (int u = 0; u < 4; u++) {
                    o[u]  = __shfl_sync(0xffffffffu, off1, j + u);
                    wp[u] = __shfl_sync(0xffffffffu, wp1,  j + u);
                }
                uint4 v[4];
                #pragma unroll
                for (int u = 0; u < 4; u++)
                    v[u] = __ldg((const uint4*)(fbase + (o[u] + laneByte)));
                #pragma unroll
                for (int u = 0; u < 4; u++) {
                    unsigned hb = loSide ? (wp[u] & 0xffffu) : (wp[u] >> 16);
                    __half2 wh = __half2half2(*reinterpret_cast<__half*>(&hb));
                    a10 = __hfma2(*reinterpret_cast<__half2*>(&v[u].x), wh, a10);
                    a11 = __hfma2(*reinterpret_cast<__half2*>(&v[u].y), wh, a11);
                    a12 = __hfma2(*reinterpret_cast<__half2*>(&v[u].z), wh, a12);
                    a13 = __hfma2(*reinterpret_cast<__half2*>(&v[u].w), wh, a13);
                }
            }
            for (; j < num; j++) {
                unsigned o  = __shfl_sync(0xffffffffu, off1, j);
                unsigned wp = __shfl_sync(0xffffffffu, wp1,  j);
                unsigned hb = loSide ? (wp & 0xffffu) : (wp >> 16);
                __half2 wh = __half2half2(*reinterpret_cast<__half*>(&hb));
                uint4 v = __ldg((const uint4*)(fbase + (o + laneByte)));
                a10 = __hfma2(*reinterpret_cast<__half2*>(&v.x), wh, a10);
                a11 = __hfma2(*reinterpret_cast<__half2*>(&v.y), wh, a11);
                a12 = __hfma2(*reinterpret_cast<__half2*>(&v.z), wh, a12);
                a13 = __hfma2(*reinterpret_cast<__half2*>(&v.w), wh, a13);
            }
        }
        base0 += 32; base1 += 32;
    }
    #pragma unroll
    for (int o = 16; o; o >>= 1) {
        den0a += __shfl_xor_sync(0xffffffffu, den0a, o);
        den0b += __shfl_xor_sync(0xffffffffu, den0b, o);
        den1a += __shfl_xor_sync(0xffffffffu, den1a, o);
        den1b += __shfl_xor_sync(0xffffffffu, den1b, o);
    }
    int row = loSide ? ra : rb;
    int lo = lane & 15;
    {
        float den = loSide ? den0a : den0b;
        float inv = (den > 0.f) ? (1.0f / den) : 0.f;
        __half2 hinv = __float2half2_rn(inv);
        uint4 val;
        __half2 t0 = __hmul2(a00, hinv), t1 = __hmul2(a01, hinv);
        __half2 t2 = __hmul2(a02, hinv), t3 = __hmul2(a03, hinv);
        val.x = *reinterpret_cast<uint32_t*>(&t0);
        val.y = *reinterpret_cast<uint32_t*>(&t1);
        val.z = *reinterpret_cast<uint32_t*>(&t2);
        val.w = *reinterpret_cast<uint32_t*>(&t3);
        uint4* dst = (uint4*)((char*)g_Y + ((long)row * NPAD + node0) * 256) + lo;
        __stcs(dst, val);
    }
    if (has1) {
        float den = loSide ? den1a : den1b;
        float inv = (den > 0.f) ? (1.0f / den) : 0.f;
        __half2 hinv = __float2half2_rn(inv);
        uint4 val;
        __half2 t0 = __hmul2(a10, hinv), t1 = __hmul2(a11, hinv);
        __half2 t2 = __hmul2(a12, hinv), t3 = __hmul2(a13, hinv);
        val.x = *reinterpret_cast<uint32_t*>(&t0);
        val.y = *reinterpret_cast<uint32_t*>(&t1);
        val.z = *reinterpret_cast<uint32_t*>(&t2);
        val.w = *reinterpret_cast<uint32_t*>(&t3);
        uint4* dst = (uint4*)((char*)g_Y + ((long)row * NPAD + node0 + 1) * 256) + lo;
        __stcs(dst, val);
    }
}

// ============ 5) mma.sync fp16 GEMM, cp.async double-buffered, ldmatrix, single sync ============
#define AS_OFF 0
#define BS_OFF 36864
#define BC_OFF 73728
#define GEMM_SMEM_BYTES (73728 + 512)
#define BUFB 18432

__device__ __forceinline__ void mma_f16(float* c, const uint32_t* a, const uint32_t* b) {
    asm volatile(
        "mma.sync.aligned.m16n8k16.row.col.f32.f16.f16.f32 "
        "{%0,%1,%2,%3}, {%4,%5,%6,%7}, {%8,%9}, {%0,%1,%2,%3};"
        : "+f"(c[0]), "+f"(c[1]), "+f"(c[2]), "+f"(c[3])
        : "r"(a[0]), "r"(a[1]), "r"(a[2]), "r"(a[3]), "r"(b[0]), "r"(b[1]));
}
__device__ __forceinline__ void ldsm_x4(uint32_t* r, uint32_t addr) {
    asm volatile("ldmatrix.sync.aligned.m8n8.x4.shared.b16 {%0,%1,%2,%3}, [%4];"
                 : "=r"(r[0]), "=r"(r[1]), "=r"(r[2]), "=r"(r[3]) : "r"(addr));
}

__global__ void __launch_bounds__(256, 2) k_gemm_mma(
    const float* __restrict__ lam, const float* __restrict__ bias,
    const float* __restrict__ fdst, float* __restrict__ out, int n) {
    extern __shared__ char smc[];
    float* bcs = (float*)(smc + BC_OFF);
    uint32_t sm_base = smem_u32(smc);

    int tid = threadIdx.x, wid = tid >> 5, lane = tid & 31;
    int wm = wid & 1, wn = wid >> 1;
    int row0 = blockIdx.x * 128;
    int g = lane >> 2, q = lane & 3;

    if (tid < 128) {
        float s = 0.f;
        #pragma unroll
        for (int t = 0; t < 4; t++)
            s += lam[t] * (bias[(2 * t) * DD + tid] + bias[(2 * t + 1) * DD + tid]);
        bcs[tid] = s;
    }

    float acc[4][4][4];
    #pragma unroll
    for (int i = 0; i < 4; i++)
        #pragma unroll
        for (int j = 0; j < 4; j++)
            #pragma unroll
            for (int t = 0; t < 4; t++) acc[i][j][t] = 0.f;

    int lrow = tid >> 1;
    int lseg = (tid & 1) * 64;

    uint32_t aLaneOff = (uint32_t)(((((lane >> 3) & 1) * 8) + (lane & 7)) * 144 + (lane >> 4) * 16);
    uint32_t bLaneOff = (uint32_t)((((lane >> 4) * 8) + (lane & 7)) * 144 + ((lane >> 3) & 1) * 16);

    auto issue = [&](int c, int buf) {
        int r = c >> 1;
        int koff = (c & 1) * 128;
        const char* ys = (const char*)g_Y + ((long)r * NPAD + row0 + lrow) * 256 + koff + lseg;
        const char* bs = (const char*)g_Bt + ((long)r * DD + lrow) * 256 + koff + lseg;
        uint32_t ad = sm_base + AS_OFF + (uint32_t)buf * BUFB + (uint32_t)lrow * 144 + lseg;
        uint32_t bd = sm_base + BS_OFF + (uint32_t)buf * BUFB + (uint32_t)lrow * 144 + lseg;
        #pragma unroll
        for (int i = 0; i < 4; i++) {
            cp16(ad + i * 16, ys + i * 16);
            cp16(bd + i * 16, bs + i * 16);
        }
        CP_COMMIT();
    };

    issue(0, 0);
    #pragma unroll 1
    for (int c = 0; c < 16; c++) {
        int buf = c & 1;
        CP_WAIT(0);
        __syncthreads();          // data of chunk c visible to all; all warps done with buf^1
        if (c < 15) issue(c + 1, buf ^ 1);
        uint32_t Ab = sm_base + AS_OFF + (uint32_t)buf * BUFB;
        uint32_t Bb = sm_base + BS_OFF + (uint32_t)buf * BUFB;
        #pragma unroll
        for (int ks = 0; ks < 4; ks++) {
            uint32_t a[4][4], b[4][2];
            #pragma unroll
            for (int mf = 0; mf < 4; mf++) {
                uint32_t addr = Ab + (uint32_t)((wm * 64 + mf * 16) * 144 + ks * 32) + aLaneOff;
                ldsm_x4(a[mf], addr);
            }
            #pragma unroll
            for (int np = 0; np < 2; np++) {
                uint32_t r4[4];
                uint32_t addr = Bb + (uint32_t)((wn * 32 + np * 16) * 144 + ks * 32) + bLaneOff;
                ldsm_x4(r4, addr);
                b[np * 2][0] = r4[0]; b[np * 2][1] = r4[1];
                b[np * 2 + 1][0] = r4[2]; b[np * 2 + 1][1] = r4[3];
            }
            #pragma unroll
            for (int mf = 0; mf < 4; mf++)
                #pragma unroll
                for (int nf = 0; nf < 4; nf++)
                    mma_f16(acc[mf][nf], a[mf], b[nf]);
        }
    }

    float cdst = 2.0f * (__ldg(&lam[0]) + __ldg(&lam[1]) + __ldg(&lam[2]) + __ldg(&lam[3]));
    float2* out2 = (float2*)out;
    const float2* fd2 = (const float2*)fdst;
    #pragma unroll
    for (int mf = 0; mf < 4; mf++) {
        #pragma unroll
        for (int half = 0; half < 2; half++) {
            int row = row0 + wm * 64 + mf * 16 + g + half * 8;
            if (row >= n) continue;
            #pragma unroll
            for (int nf = 0; nf < 4; nf++) {
                int col = wn * 32 + nf * 8 + 2 * q;
                float2 fd = fd2[(long)row * 64 + (col >> 1)];
                float c0 = acc[mf][nf][half * 2 + 0];
                float c1 = acc[mf][nf][half * 2 + 1];
                float2 o;
                o.x = c0 + cdst * fd.x + bcs[col];
                o.y = c1 + cdst * fd.y + bcs[col + 1];
                out2[(long)row * 64 + (col >> 1)] = o;
            }
        }
    }
}

extern "C" void kernel_launch(void* const* d_in, const int* in_sizes, int n_in,
                              void* d_out, int out_size) {
    const float* fsrc = (const float*)d_in[0];
    const float* fdst = (const float*)d_in[1];
    const int*   isrc = (const int*)d_in[2];
    const int*   idst = (const int*)d_in[3];
    const int*   xsrc = (const int*)d_in[4];
    const int*   xdst = (const int*)d_in[5];
    const float* W    = (const float*)d_in[6];
    const float* al   = (const float*)d_in[7];
    const float* ar   = (const float*)d_in[8];
    const float* bias = (const float*)d_in[9];
    const float* lam  = (const float*)d_in[10];
    float* out = (float*)d_out;

    int n = in_sizes[0] / DD;
    int E = in_sizes[2];
    int len = 4 * n;
    int nbScan = (len + 1023) / 1024;
    int histB = (4 * E + 255) / 256;
    int fillB = (2 * E + 255) / 256;
    int elrB1024 = (n + 31) / 32;

    static int configured = 0;
    if (!configured) {
        cudaFuncSetAttribute(k_gemm_mma, cudaFuncAttributeMaxDynamicSharedMemorySize,
                             GEMM_SMEM_BYTES);
        configured = 1;
    }

    k_hist_prep<<<histB, 256>>>(isrc, idst, xsrc, xdst, W, al, ar, lam, n, E);
    k_scan_elr<<<nbScan + elrB1024, 1024>>>(fsrc, fdst, n, len, nbScan);
    k_fill_w<<<fillB, 256>>>(isrc, idst, xsrc, xdst, n, E);
    k_agg<<<dim3((n + 15) / 16, 4), 256>>>(n, E);
    k_gemm_mma<<<(n + 127) / 128, 256, GEMM_SMEM_BYTES>>>(lam, bias, fdst, out, n);
}

// round 16
// speedup vs baseline: 1.0635x; 1.0086x over previous
#include <cuda_runtime.h>
#include <cuda_bf16.h>
#include <cuda_fp16.h>
#include <math.h>
#include <stdint.h>

#define MAXN 100000
#define NPAD 100096
#define MAXE 600000
#define DD 128

// ---------------- static device scratch (zero-initialized at load) ----------------
__device__ __align__(256) __half g_Y[8L * NPAD * DD];   // Y_r = S_r X_r (fp16)
__device__ __align__(256) __half g_Bt[8 * DD * DD];     // fp16(lam * W^T)
__device__ __align__(256) __half g_fI[MAXN * 2 * DD];   // node: 256B fsrc | 256B fdst (fp16)
__device__ float4 g_P[2 * MAXN];   // src-side: (el_f.ra, el_f.rb, er_r.ra, er_r.rb)
__device__ float4 g_Q[2 * MAXN];   // dst-side: (er_f.ra, er_f.rb, el_r.ra, el_r.rb)
__device__ float g_wal[8 * DD];
__device__ float g_war[8 * DD];
__device__ int   g_cnt[4 * MAXN];     // zeroed at load; re-zeroed by scan each run
__device__ int   g_rowptr[4 * MAXN];
__device__ int   g_cursor[4 * MAXN];
__device__ int   g_col[4 * MAXE];
__device__ unsigned g_w[4 * MAXE];    // per-slot half2(wa, wb)
// decoupled-lookback state (reset by last scan block each run)
__device__ volatile int g_stat[512];
__device__ int g_aggv[512];
__device__ int g_prefv[512];
__device__ int g_done;

__device__ __forceinline__ uint32_t smem_u32(const void* p) {
    uint32_t a;
    asm("{ .reg .u64 t; cvta.to.shared.u64 t, %1; cvt.u32.u64 %0, t; }" : "=r"(a) : "l"(p));
    return a;
}
__device__ __forceinline__ void cp16(uint32_t dst, const void* src) {
    asm volatile("cp.async.ca.shared.global [%0], [%1], 16;" :: "r"(dst), "l"(src));
}
#define CP_COMMIT() asm volatile("cp.async.commit_group;" ::: "memory")
#define CP_WAIT(N)  asm volatile("cp.async.wait_group %0;" :: "n"(N) : "memory")

__device__ __forceinline__ float lrelu(float x) { return x > 0.f ? x : 0.2f * x; }

// ============ 1) hist + (blocks 0-7) wal/war/Bt prep ============
__global__ void k_hist_prep(const int* __restrict__ isrc, const int* __restrict__ idst,
                            const int* __restrict__ xsrc, const int* __restrict__ xdst,
                            const float* __restrict__ W, const float* __restrict__ al,
                            const float* __restrict__ ar, const float* __restrict__ lam,
                            int n, int E) {
    int bid = blockIdx.x, tid = threadIdx.x;
    if (bid < 8) {
        int r = bid;
        if (tid < 128) {
            const float* Wr  = W + r * DD * DD + tid * DD;
            const float* alr = al + r * DD;
            const float* arr = ar + r * DD;
            float sl = 0.f, sr = 0.f;
            #pragma unroll 8
            for (int j = 0; j < DD; j++) { float w = Wr[j]; sl += w * alr[j]; sr += w * arr[j]; }
            g_wal[r * DD + tid] = sl;
            g_war[r * DD + tid] = sr;
        }
        float lr = lam[r >> 1];
        for (int i = tid; i < DD * DD; i += 256) {
            int nn = i >> 7, kk = i & 127;
            g_Bt[r * DD * DD + i] = __float2half_rn(lr * W[(r * DD + kk) * DD + nn]);
        }
    }
    int t = bid * 256 + tid;
    if (t >= 4 * E) return;
    int s = t / E, e = t - s * E;
    int key = (s == 0) ? idst[e] : (s == 1) ? xdst[e] : (s == 2) ? isrc[e] : xsrc[e];
    atomicAdd(&g_cnt[s * n + key], 1);
}

// ============ 2) merged: decoupled-lookback scan + elr (endpoint-packed) ============
__global__ void __launch_bounds__(1024) k_scan_elr(
    const float* __restrict__ fsrc, const float* __restrict__ fdst,
    int n, int len, int nbScan) {
    __shared__ int sm[1024];
    __shared__ int s_pref;
    __shared__ float4 swal[8 * 32], swar[8 * 32];
    int bid = blockIdx.x, tid = threadIdx.x;

    if (bid < nbScan) {
        int b = bid;
        int i = b * 1024 + tid;
        int v = (i < len) ? g_cnt[i] : 0;
        sm[tid] = v;
        __syncthreads();
        for (int off = 1; off < 1024; off <<= 1) {
            int t = (tid >= off) ? sm[tid - off] : 0;
            __syncthreads();
            sm[tid] += t;
            __syncthreads();
        }
        int incl = sm[tid];
        if (tid == 1023) {
            int total = incl;
            if (b == 0) {
                g_prefv[0] = total;
                __threadfence();
                g_stat[0] = 2;
                s_pref = 0;
            } else {
                g_aggv[b] = total;
                __threadfence();
                g_stat[b] = 1;
                int pref = 0;
                for (int j = b - 1; j >= 0;) {
                    int st;
                    do { st = g_stat[j]; } while (st == 0);
                    __threadfence();
                    if (st == 2) { pref += g_prefv[j]; break; }
                    pref += g_aggv[j]; j--;
                }
                g_prefv[b] = pref + total;
                __threadfence();
                g_stat[b] = 2;
                s_pref = pref;
            }
        }
        __syncthreads();
        int pref = s_pref;
        if (i < len) {
            int excl = incl - v + pref;
            g_rowptr[i] = excl;
            g_cursor[i] = excl;
            g_cnt[i] = 0;
        }
        __syncthreads();
        if (tid == 0) {
            int d = atomicAdd(&g_done, 1);
            if (d == nbScan - 1) {
                for (int j = 0; j < nbScan; j++) g_stat[j] = 0;
                g_done = 0;
                __threadfence();
            }
        }
        return;
    }

    // ---- elr + fp16 mirror (32 nodes per 1024-thread block) ----
    if (tid < 256) {
        swal[tid] = ((const float4*)g_wal)[tid];
        swar[tid] = ((const float4*)g_war)[tid];
    }
    __syncthreads();
    int warp = tid >> 5, lane = tid & 31;
    int node = (bid - nbScan) * 32 + warp;
    if (node >= n) return;
    float4 fs = ((const float4*)fsrc)[(long)node * 32 + lane];
    float4 fd = ((const float4*)fdst)[(long)node * 32 + lane];
    {
        __half2 a0 = __floats2half2_rn(fs.x, fs.y);
        __half2 a1 = __floats2half2_rn(fs.z, fs.w);
        __half2 b0 = __floats2half2_rn(fd.x, fd.y);
        __half2 b1 = __floats2half2_rn(fd.z, fd.w);
        uint2 ua, ub;
        ua.x = *reinterpret_cast<uint32_t*>(&a0); ua.y = *reinterpret_cast<uint32_t*>(&a1);
        ub.x = *reinterpret_cast<uint32_t*>(&b0); ub.y = *reinterpret_cast<uint32_t*>(&b1);
        ((uint2*)g_fI)[((long)node << 6) + lane] = ua;
        ((uint2*)g_fI)[((long)node << 6) + 32 + lane] = ub;
    }
    float p[16];
    #pragma unroll
    for (int r = 0; r < 8; r++) {
        float4 wl = swal[r * 32 + lane];
        float4 wr = swar[r * 32 + lane];
        bool useSrc = (r == 0 || r == 1 || r == 4 || r == 5);
        float4 x = useSrc ? fs : fd;
        p[r]     = x.x * wl.x + x.y * wl.y + x.z * wl.z + x.w * wl.w;
        p[8 + r] = fd.x * wr.x + fd.y * wr.y + fd.z * wr.z + fd.w * wr.w;
    }
    #pragma unroll
    for (int i = 0; i < 16; i++)
        #pragma unroll
        for (int o = 16; o; o >>= 1) p[i] += __shfl_xor_sync(0xffffffffu, p[i], o);
    if (lane == 0) {
        g_P[node]              = make_float4(p[0], p[2], p[12], p[14]);
        g_Q[node]              = make_float4(p[8], p[10], p[4],  p[6]);
        g_P[(long)MAXN + node] = make_float4(p[1], p[3], p[13], p[15]);
        g_Q[(long)MAXN + node] = make_float4(p[9], p[11], p[5],  p[7]);
    }
}

// ============ 3) fill + weights for ONE edge-pair p (fwd + rev together) ============
__global__ void k_fill_w(const int* __restrict__ esrc, const int* __restrict__ edst,
                         int p, int n, int E) {
    int e = blockIdx.x * blockDim.x + threadIdx.x;
    if (e >= E) return;
    int src = __ldg(&esrc[e]);
    int dst = __ldg(&edst[e]);
    float4 Ps = __ldg(&g_P[(long)p * MAXN + src]);
    float4 Qd = __ldg(&g_Q[(long)p * MAXN + dst]);
    long pn = (long)p * n;
    {
        int pos = atomicAdd(&g_cursor[pn + dst], 1);
        g_col[pos] = src;
        __half2 hw = __floats2half2_rn(__expf(lrelu(Ps.x + Qd.x)),
                                       __expf(lrelu(Ps.y + Qd.y)));
        g_w[pos] = *reinterpret_cast<unsigned*>(&hw);
    }
    {
        int pos = atomicAdd(&g_cursor[pn + 2L * n + src], 1);
        g_col[pos] = dst;
        __half2 hw = __floats2half2_rn(__expf(lrelu(Qd.z + Ps.z)),
                                       __expf(lrelu(Qd.w + Ps.w)));
        g_w[pos] = *reinterpret_cast<unsigned*>(&hw);
    }
}

// ============ 4) gather agg: 2 consecutive nodes per warp; structures s = 2*blockIdx.y + sOff ============
__global__ void __launch_bounds__(256) k_agg(int n, int E, int sOff) {
    int s = blockIdx.y * 2 + sOff;
    int warp = threadIdx.x >> 5, lane = threadIdx.x & 31;
    int node0 = blockIdx.x * 16 + warp * 2;
    if (node0 >= n) return;
    bool has1 = (node0 + 1) < n;
    int ra = (s < 2) ? s : s + 2;
    int rb = ra + 2;
    long idx = (long)s * n + node0;
    int start0 = g_rowptr[idx];
    int end0   = g_rowptr[idx + 1];
    int start1 = end0;
    int end1;
    if (has1) end1 = (idx + 2 < 4L * n) ? g_rowptr[idx + 2] : 4 * E;
    else      end1 = start1;

    __half2 a00 = __float2half2_rn(0.f), a01 = a00, a02 = a00, a03 = a00;
    __half2 a10 = a00, a11 = a00, a12 = a00, a13 = a00;
    float den0a = 0.f, den0b = 0.f, den1a = 0.f, den1b = 0.f;

    const char* fbase = (const char*)g_fI;
    unsigned laneByte = (unsigned)lane * 16u;
    bool loSide = lane < 16;

    int base0 = start0, base1 = start1;
    while (base0 < end0 || base1 < end1) {
        unsigned off0 = 0, wp0 = 0, off1 = 0, wp1 = 0;
        if (base0 < end0) {
            int k = base0 + lane;
            if (k < end0) {
                int c = __ldg(&g_col[k]);
                wp0 = __ldg(&g_w[k]);
                off0 = (unsigned)c << 9;
            }
        }
        if (base1 < end1) {
            int k = base1 + lane;
            if (k < end1) {
                int c = __ldg(&g_col[k]);
                wp1 = __ldg(&g_w[k]);
                off1 = (unsigned)c << 9;
            }
        }
        {
            __half2 h0 = *reinterpret_cast<__half2*>(&wp0);
            float2 f0 = __half22float2(h0);
            den0a += f0.x; den0b += f0.y;
            __half2 h1 = *reinterpret_cast<__half2*>(&wp1);
            float2 f1 = __half22float2(h1);
            den1a += f1.x; den1b += f1.y;
        }
        if (base0 < end0) {
            int num = min(32, end0 - base0);
            int j = 0;
            for (; j + 3 < num; j += 4) {
                unsigned o[4], wp[4];
                #pragma unroll
                for (int u = 0; u < 4; u++) {
                    o[u]  = __shfl_sync(0xffffffffu, off0, j + u);
                    wp[u] = __shfl_sync(0xffffffffu, wp0,  j + u);
                }
                uint4 v[4];
                #pragma unroll
                for (int u = 0; u < 4; u++)
                    v[u] = __ldg((const uint4*)(fbase + (o[u] + laneByte)));
                #pragma unroll
                for (int u = 0; u < 4; u++) {
                    unsigned hb = loSide ? (wp[u] & 0xffffu) : (wp[u] >> 16);
                    __half2 wh = __half2half2(*reinterpret_cast<__half*>(&hb));
                    a00 = __hfma2(*reinterpret_cast<__half2*>(&v[u].x), wh, a00);
                    a01 = __hfma2(*reinterpret_cast<__half2*>(&v[u].y), wh, a01);
                    a02 = __hfma2(*reinterpret_cast<__half2*>(&v[u].z), wh, a02);
                    a03 = __hfma2(*reinterpret_cast<__half2*>(&v[u].w), wh, a03);
                }
            }
            for (; j < num; j++) {
                unsigned o  = __shfl_sync(0xffffffffu, off0, j);
                unsigned wp = __shfl_sync(0xffffffffu, wp0,  j);
                unsigned hb = loSide ? (wp & 0xffffu) : (wp >> 16);
                __half2 wh = __half2half2(*reinterpret_cast<__half*>(&hb));
                uint4 v = __ldg((const uint4*)(fbase + (o + laneByte)));
                a00 = __hfma2(*reinterpret_cast<__half2*>(&v.x), wh, a00);
                a01 = __hfma2(*reinterpret_cast<__half2*>(&v.y), wh, a01);
                a02 = __hfma2(*reinterpret_cast<__half2*>(&v.z), wh, a02);
                a03 = __hfma2(*reinterpret_cast<__half2*>(&v.w), wh, a03);
            }
        }
        if (base1 < end1) {
            int num = min(32, end1 - base1);
            int j = 0;
            for (; j + 3 < num; j += 4) {
                unsigned o[4], wp[4];
                #pragma unroll
                for (int u = 0; u < 4; u++) {
                    o[u]  = __shfl_sync(0xffffffffu, off1, j + u);
                    wp[u] = __shfl_sync(0xffffffffu, wp1,  j + u);
                }
                uint4 v[4];
                #pragma unroll
                for (int u = 0; u < 4; u++)
                    v[u] = __ldg((const uint4*)(fbase + (o[u] + laneByte)));
                #pragma unroll
                for (int u = 0; u < 4; u++) {
                    unsigned hb = loSide ? (wp[u] & 0xffffu) : (wp[u] >> 16);
                    __half2 wh = __half2half2(*reinterpret_cast<__half*>(&hb));
                    a10 = __hfma2(*reinterpret_cast<__half2*>(&v[u].x), wh, a10);
                    a11 = __hfma2(*reinterpret_cast<__half2*>(&v[u].y), wh, a11);
                    a12 = __hfma2(*reinterpret_cast<__half2*>(&v[u].z), wh, a12);
                    a13 = __hfma2(*reinterpret_cast<__half2*>(&v[u].w), wh, a13);
                }
            }
            for (; j < num; j++) {
                unsigned o  = __shfl_sync(0xffffffffu, off1, j);
                unsigned wp = __shfl_sync(0xffffffffu, wp1,  j);
                unsigned hb = loSide ? (wp & 0xffffu) : (wp >> 16);
                __half2 wh = __half2half2(*reinterpret_cast<__half*>(&hb));
                uint4 v = __ldg((const uint4*)(fbase + (o + laneByte)));
                a10 = __hfma2(*reinterpret_cast<__half2*>(&v.x), wh, a10);
                a11 = __hfma2(*reinterpret_cast<__half2*>(&v.y), wh, a11);
                a12 = __hfma2(*reinterpret_cast<__half2*>(&v.z), wh, a12);
                a13 = __hfma2(*reinterpret_cast<__half2*>(&v.w), wh, a13);
            }
        }
        base0 += 32; base1 += 32;
    }
    #pragma unroll
    for (int o = 16; o; o >>= 1) {
        den0a += __shfl_xor_sync(0xffffffffu, den0a, o);
        den0b += __shfl_xor_sync(0xffffffffu, den0b, o);
        den1a += __shfl_xor_sync(0xffffffffu, den1a, o);
        den1b += __shfl_xor_sync(0xffffffffu, den1b, o);
    }
    int row = loSide ? ra : rb;
    int lo = lane & 15;
    {
        float den = loSide ? den0a : den0b;
        float inv = (den > 0.f) ? (1.0f / den) : 0.f;
        __half2 hinv = __float2half2_rn(inv);
        uint4 val;
        __half2 t0 = __hmul2(a00, hinv), t1 = __hmul2(a01, hinv);
        __half2 t2 = __hmul2(a02, hinv), t3 = __hmul2(a03, hinv);
        val.x = *reinterpret_cast<uint32_t*>(&t0);
        val.y = *reinterpret_cast<uint32_t*>(&t1);
        val.z = *reinterpret_cast<uint32_t*>(&t2);
        val.w = *reinterpret_cast<uint32_t*>(&t3);
        uint4* dst = (uint4*)((char*)g_Y + ((long)row * NPAD + node0) * 256) + lo;
        __stcs(dst, val);
    }
    if (has1) {
        float den = loSide ? den1a : den1b;
        float inv = (den > 0.f) ? (1.0f / den) : 0.f;
        __half2 hinv = __float2half2_rn(inv);
        uint4 val;
        __half2 t0 = __hmul2(a10, hinv), t1 = __hmul2(a11, hinv);
        __half2 t2 = __hmul2(a12, hinv), t3 = __hmul2(a13, hinv);
        val.x = *reinterpret_cast<uint32_t*>(&t0);
        val.y = *reinterpret_cast<uint32_t*>(&t1);
        val.z = *reinterpret_cast<uint32_t*>(&t2);
        val.w = *reinterpret_cast<uint32_t*>(&t3);
        uint4* dst = (uint4*)((char*)g_Y + ((long)row * NPAD + node0 + 1) * 256) + lo;
        __stcs(dst, val);
    }
}

// ============ 5) mma.sync fp16 GEMM, cp.async double-buffered, ldmatrix, single sync ============
#define AS_OFF 0
#define BS_OFF 36864
#define BC_OFF 73728
#define GEMM_SMEM_BYTES (73728 + 512)
#define BUFB 18432

__device__ __forceinline__ void mma_f16(float* c, const uint32_t* a, const uint32_t* b) {
    asm volatile(
        "mma.sync.aligned.m16n8k16.row.col.f32.f16.f16.f32 "
        "{%0,%1,%2,%3}, {%4,%5,%6,%7}, {%8,%9}, {%0,%1,%2,%3};"
        : "+f"(c[0]), "+f"(c[1]), "+f"(c[2]), "+f"(c[3])
        : "r"(a[0]), "r"(a[1]), "r"(a[2]), "r"(a[3]), "r"(b[0]), "r"(b[1]));
}
__device__ __forceinline__ void ldsm_x4(uint32_t* r, uint32_t addr) {
    asm volatile("ldmatrix.sync.aligned.m8n8.x4.shared.b16 {%0,%1,%2,%3}, [%4];"
                 : "=r"(r[0]), "=r"(r[1]), "=r"(r[2]), "=r"(r[3]) : "r"(addr));
}

__global__ void __launch_bounds__(256, 2) k_gemm_mma(
    const float* __restrict__ lam, const float* __restrict__ bias,
    const float* __restrict__ fdst, float* __restrict__ out, int n) {
    extern __shared__ char smc[];
    float* bcs = (float*)(smc + BC_OFF);
    uint32_t sm_base = smem_u32(smc);

    int tid = threadIdx.x, wid = tid >> 5, lane = tid & 31;
    int wm = wid & 1, wn = wid >> 1;
    int row0 = blockIdx.x * 128;
    int g = lane >> 2, q = lane & 3;

    if (tid < 128) {
        float s = 0.f;
        #pragma unroll
        for (int t = 0; t < 4; t++)
            s += lam[t] * (bias[(2 * t) * DD + tid] + bias[(2 * t + 1) * DD + tid]);
        bcs[tid] = s;
    }

    float acc[4][4][4];
    #pragma unroll
    for (int i = 0; i < 4; i++)
        #pragma unroll
        for (int j = 0; j < 4; j++)
            #pragma unroll
            for (int t = 0; t < 4; t++) acc[i][j][t] = 0.f;

    int lrow = tid >> 1;
    int lseg = (tid & 1) * 64;

    uint32_t aLaneOff = (uint32_t)(((((lane >> 3) & 1) * 8) + (lane & 7)) * 144 + (lane >> 4) * 16);
    uint32_t bLaneOff = (uint32_t)((((lane >> 4) * 8) + (lane & 7)) * 144 + ((lane >> 3) & 1) * 16);

    auto issue = [&](int c, int buf) {
        int r = c >> 1;
        int koff = (c & 1) * 128;
        const char* ys = (const char*)g_Y + ((long)r * NPAD + row0 + lrow) * 256 + koff + lseg;
        const char* bs = (const char*)g_Bt + ((long)r * DD + lrow) * 256 + koff + lseg;
        uint32_t ad = sm_base + AS_OFF + (uint32_t)buf * BUFB + (uint32_t)lrow * 144 + lseg;
        uint32_t bd = sm_base + BS_OFF + (uint32_t)buf * BUFB + (uint32_t)lrow * 144 + lseg;
        #pragma unroll
        for (int i = 0; i < 4; i++) {
            cp16(ad + i * 16, ys + i * 16);
            cp16(bd + i * 16, bs + i * 16);
        }
        CP_COMMIT();
    };

    issue(0, 0);
    #pragma unroll 1
    for (int c = 0; c < 16; c++) {
        int buf = c & 1;
        CP_WAIT(0);
        __syncthreads();
        if (c < 15) issue(c + 1, buf ^ 1);
        uint32_t Ab = sm_base + AS_OFF + (uint32_t)buf * BUFB;
        uint32_t Bb = sm_base + BS_OFF + (uint32_t)buf * BUFB;
        #pragma unroll
        for (int ks = 0; ks < 4; ks++) {
            uint32_t a[4][4], b[4][2];
            #pragma unroll
            for (int mf = 0; mf < 4; mf++) {
                uint32_t addr = Ab + (uint32_t)((wm * 64 + mf * 16) * 144 + ks * 32) + aLaneOff;
                ldsm_x4(a[mf], addr);
            }
            #pragma unroll
            for (int np = 0; np < 2; np++) {
                uint32_t r4[4];
                uint32_t addr = Bb + (uint32_t)((wn * 32 + np * 16) * 144 + ks * 32) + bLaneOff;
                ldsm_x4(r4, addr);
                b[np * 2][0] = r4[0]; b[np * 2][1] = r4[1];
                b[np * 2 + 1][0] = r4[2]; b[np * 2 + 1][1] = r4[3];
            }
            #pragma unroll
            for (int mf = 0; mf < 4; mf++)
                #pragma unroll
                for (int nf = 0; nf < 4; nf++)
                    mma_f16(acc[mf][nf], a[mf], b[nf]);
        }
    }

    float cdst = 2.0f * (__ldg(&lam[0]) + __ldg(&lam[1]) + __ldg(&lam[2]) + __ldg(&lam[3]));
    float2* out2 = (float2*)out;
    const float2* fd2 = (const float2*)fdst;
    #pragma unroll
    for (int mf = 0; mf < 4; mf++) {
        #pragma unroll
        for (int half = 0; half < 2; half++) {
            int row = row0 + wm * 64 + mf * 16 + g + half * 8;
            if (row >= n) continue;
            #pragma unroll
            for (int nf = 0; nf < 4; nf++) {
                int col = wn * 32 + nf * 8 + 2 * q;
                float2 fd = fd2[(long)row * 64 + (col >> 1)];
                float c0 = acc[mf][nf][half * 2 + 0];
                float c1 = acc[mf][nf][half * 2 + 1];
                float2 o;
                o.x = c0 + cdst * fd.x + bcs[col];
                o.y = c1 + cdst * fd.y + bcs[col + 1];
                out2[(long)row * 64 + (col >> 1)] = o;
            }
        }
    }
}

extern "C" void kernel_launch(void* const* d_in, const int* in_sizes, int n_in,
                              void* d_out, int out_size) {
    const float* fsrc = (const float*)d_in[0];
    const float* fdst = (const float*)d_in[1];
    const int*   isrc = (const int*)d_in[2];
    const int*   idst = (const int*)d_in[3];
    const int*   xsrc = (const int*)d_in[4];
    const int*   xdst = (const int*)d_in[5];
    const float* W    = (const float*)d_in[6];
    const float* al   = (const float*)d_in[7];
    const float* ar   = (const float*)d_in[8];
    const float* bias = (const float*)d_in[9];
    const float* lam  = (const float*)d_in[10];
    float* out = (float*)d_out;

    int n = in_sizes[0] / DD;
    int E = in_sizes[2];
    int len = 4 * n;
    int nbScan = (len + 1023) / 1024;
    int histB = (4 * E + 255) / 256;
    int fillB = (E + 255) / 256;
    int elrB1024 = (n + 31) / 32;

    static int configured = 0;
    static cudaStream_t s1;
    static cudaEvent_t evFork, evJoin;
    if (!configured) {
        cudaFuncSetAttribute(k_gemm_mma, cudaFuncAttributeMaxDynamicSharedMemorySize,
                             GEMM_SMEM_BYTES);
        cudaStreamCreateWithFlags(&s1, cudaStreamNonBlocking);
        cudaEventCreateWithFlags(&evFork, cudaEventDisableTiming);
        cudaEventCreateWithFlags(&evJoin, cudaEventDisableTiming);
        configured = 1;
    }

    k_hist_prep<<<histB, 256>>>(isrc, idst, xsrc, xdst, W, al, ar, lam, n, E);
    k_scan_elr<<<nbScan + elrB1024, 1024>>>(fsrc, fdst, n, len, nbScan);

    // fork: intra chain (p=0, structures 0&2) on stream 0; inter chain (p=1, 1&3) on s1
    cudaEventRecord(evFork, 0);
    cudaStreamWaitEvent(s1, evFork, 0);

    k_fill_w<<<fillB, 256, 0, 0>>>(isrc, idst, 0, n, E);
    k_agg<<<dim3((n + 15) / 16, 2), 256, 0, 0>>>(n, E, 0);

    k_fill_w<<<fillB, 256, 0, s1>>>(xsrc, xdst, 1, n, E);
    k_agg<<<dim3((n + 15) / 16, 2), 256, 0, s1>>>(n, E, 1);
    cudaEventRecord(evJoin, s1);

    cudaStreamWaitEvent(0, evJoin, 0);
    k_gemm_mma<<<(n + 127) / 128, 256, GEMM_SMEM_BYTES>>>(lam, bias, fdst, out, n);
}